// round 2
// baseline (speedup 1.0000x reference)
#include <cuda_runtime.h>
#include <math.h>

// ----------------------------------------------------------------------------
// BidirectionalPropagation (BasicVSR++ style) on GB300.
// B=1, T=8, C=64, H=W=96, DG=16. All fp32.
//
// Structure:
//   conv3x3_k : direct 3x3 conv, SAME pad, input given as up to three 64-ch
//               blocks (nullptr => zeros). Optional lrelu + residual add fused.
//   dcn_sample_k : modulated deformable sampling -> cols[1152][9216]
//                  (applies 5*tanh to offsets and sigmoid to masks inline)
//   gemm_k    : out[64,9216] = W[64,K] @ in[K,9216] + bias (+add). Used for the
//               DCN einsum (K=1152) and the fusion conv1x1 (K=128, split inputs).
// ----------------------------------------------------------------------------

#define HWP 9216          // 96*96
#define CH  (64 * HWP)    // one 64-channel feature map

// Scratch (static device globals; no allocation at runtime)
__device__ float g_fb[8][CH];          // backward branch features per frame
__device__ float g_ff[8][CH];          // forward branch features per frame
__device__ float g_hA[CH];
__device__ float g_hB[CH];
__device__ float g_out4[432 * HWP];    // raw offset/mask conv output
__device__ float g_cols[1152 * HWP];   // deformable-sampled columns
__device__ float g_dcn[CH];            // DCN output (aligned prop)

// ---------------------------------------------------------------------------
// conv3x3: tile 16x16 pixels, 128 threads (each computes rows ty and ty+8),
// 16 output channels per block. Input channels streamed in superblocks of 4.
// grid = (36, Cout/16)
// ---------------------------------------------------------------------------
__global__ __launch_bounds__(128) void conv3x3_k(
    const float* __restrict__ in0, const float* __restrict__ in1,
    const float* __restrict__ in2, int cinBlocks,
    const float* __restrict__ wgt, const float* __restrict__ bias,
    const float* __restrict__ addsrc, float* __restrict__ out, int act)
{
    __shared__ float s_in[4][324];   // 18x18 halo tile per cin
    __shared__ float s_w[4][144];    // 16 couts * 9 taps per cin

    const int Cin = cinBlocks * 64;
    const int tid = threadIdx.x;
    const int tileX = (blockIdx.x % 6) * 16;
    const int tileY = (blockIdx.x / 6) * 16;
    const int coBase = blockIdx.y * 16;
    const int tx = tid & 15;
    const int ty = tid >> 4;   // 0..7

    float acc0[16], acc1[16];
#pragma unroll
    for (int i = 0; i < 16; i++) { acc0[i] = 0.f; acc1[i] = 0.f; }

    const int nSuper = cinBlocks * 16;
    for (int s = 0; s < nSuper; s++) {
        const int cin0 = s * 4;
        const int blk = cin0 >> 6;
        const float* bp = (blk == 0) ? in0 : ((blk == 1) ? in1 : in2);
        __syncthreads();
        if (bp) {
            // stage input tiles (4 cins x 18x18, zero-padded at borders)
            for (int idx = tid; idx < 4 * 324; idx += 128) {
                int c = idx / 324; int rem = idx - c * 324;
                int r = rem / 18; int cc = rem - r * 18;
                int gy = tileY - 1 + r, gx = tileX - 1 + cc;
                float v = 0.f;
                if ((unsigned)gy < 96u && (unsigned)gx < 96u)
                    v = bp[((cin0 & 63) + c) * HWP + gy * 96 + gx];
                s_in[c][rem] = v;
            }
            // stage weights (4 cins x 16 couts x 9)
            for (int idx = tid; idx < 4 * 144; idx += 128) {
                int c = idx / 144; int rem = idx - c * 144;
                int co = rem / 9; int k = rem - co * 9;
                s_w[c][rem] = wgt[((coBase + co) * Cin + (cin0 + c)) * 9 + k];
            }
        }
        __syncthreads();
        if (!bp) continue;   // zero block contributes nothing

#pragma unroll
        for (int c = 0; c < 4; c++) {
            float iv0[9], iv1[9];
#pragma unroll
            for (int r = 0; r < 3; r++)
#pragma unroll
                for (int cc = 0; cc < 3; cc++) {
                    iv0[r * 3 + cc] = s_in[c][(ty + r) * 18 + (tx + cc)];
                    iv1[r * 3 + cc] = s_in[c][(ty + 8 + r) * 18 + (tx + cc)];
                }
#pragma unroll
            for (int co = 0; co < 16; co++) {
#pragma unroll
                for (int k = 0; k < 9; k++) {
                    float w = s_w[c][co * 9 + k];
                    acc0[co] = fmaf(iv0[k], w, acc0[co]);
                    acc1[co] = fmaf(iv1[k], w, acc1[co]);
                }
            }
        }
    }

    const int px0 = (tileY + ty) * 96 + tileX + tx;
    const int px1 = px0 + 8 * 96;
#pragma unroll
    for (int co = 0; co < 16; co++) {
        float b = bias[coBase + co];
        float v0 = acc0[co] + b, v1 = acc1[co] + b;
        if (act) {
            v0 = (v0 >= 0.f) ? v0 : 0.1f * v0;
            v1 = (v1 >= 0.f) ? v1 : 0.1f * v1;
        }
        if (addsrc) {
            v0 += addsrc[(coBase + co) * HWP + px0];
            v1 += addsrc[(coBase + co) * HWP + px1];
        }
        out[(coBase + co) * HWP + px0] = v0;
        out[(coBase + co) * HWP + px1] = v1;
    }
}

// ---------------------------------------------------------------------------
// Modulated deformable sampling. grid = (72, 144) = (pix/128, dg*K).
// Reads raw out4 (432ch), applies 5*tanh (offsets) / sigmoid (mask),
// bilinear-samples xin (two 64-ch blocks, in1 may be null => zeros),
// writes cols[(cin*9+k)*HWP + pix].
// ---------------------------------------------------------------------------
__global__ __launch_bounds__(128) void dcn_sample_k(
    const float* __restrict__ xin0, const float* __restrict__ xin1,
    const float* __restrict__ out4, float* __restrict__ cols)
{
    const int pix = blockIdx.x * 128 + threadIdx.x;
    const int gk = blockIdx.y;           // g*9 + k
    const int g = gk / 9, k = gk - g * 9;
    const int h = pix / 96, w = pix - h * 96;

    const float offY = 5.f * tanhf(out4[(gk * 2 + 0) * HWP + pix]);
    const float offX = 5.f * tanhf(out4[(gk * 2 + 1) * HWP + pix]);
    const float mraw = out4[(288 + gk) * HWP + pix];
    const float m = 1.f / (1.f + expf(-mraw));

    const int ky = k / 3, kx = k - ky * 3;
    const float sy = offY + (float)(h - 1 + ky);
    const float sx = offX + (float)(w - 1 + kx);
    const float y0f = floorf(sy), x0f = floorf(sx);
    const float fy = sy - y0f, fx = sx - x0f;
    const int y0 = (int)y0f, x0 = (int)x0f;

    const bool vy0 = (y0 >= 0) && (y0 < 96);
    const bool vy1 = (y0 + 1 >= 0) && (y0 + 1 < 96);
    const bool vx0 = (x0 >= 0) && (x0 < 96);
    const bool vx1 = (x0 + 1 >= 0) && (x0 + 1 < 96);
    const int cy0 = min(max(y0, 0), 95), cy1 = min(max(y0 + 1, 0), 95);
    const int cx0 = min(max(x0, 0), 95), cx1 = min(max(x0 + 1, 0), 95);

    const float w00 = (1.f - fy) * (1.f - fx) * ((vy0 && vx0) ? 1.f : 0.f);
    const float w01 = (1.f - fy) * fx         * ((vy0 && vx1) ? 1.f : 0.f);
    const float w10 = fy * (1.f - fx)         * ((vy1 && vx0) ? 1.f : 0.f);
    const float w11 = fy * fx                 * ((vy1 && vx1) ? 1.f : 0.f);

    const int i00 = cy0 * 96 + cx0, i01 = cy0 * 96 + cx1;
    const int i10 = cy1 * 96 + cx0, i11 = cy1 * 96 + cx1;

#pragma unroll
    for (int c = 0; c < 8; c++) {
        const int cin = g * 8 + c;
        const float* p = (cin < 64) ? xin0 : xin1;
        float v = 0.f;
        if (p) {
            const float* pc = p + (cin & 63) * HWP;
            v = w00 * pc[i00] + w01 * pc[i01] + w10 * pc[i10] + w11 * pc[i11];
        }
        cols[(cin * 9 + k) * HWP + pix] = v * m;
    }
}

// ---------------------------------------------------------------------------
// GEMM: out[64,HWP] = W[64,K] @ in[K,HWP] + bias (+ add).
// Input rows k < ksplit come from in0, rest from in1.
// grid = (36, 4), 128 threads, 2 pixels per thread.
// ---------------------------------------------------------------------------
__global__ __launch_bounds__(128) void gemm_k(
    const float* __restrict__ in0, const float* __restrict__ in1,
    int ksplit, int K,
    const float* __restrict__ wgt, const float* __restrict__ bias,
    const float* __restrict__ addsrc, float* __restrict__ out)
{
    __shared__ float s_w[8][16];
    const int tid = threadIdx.x;
    const int pix0 = blockIdx.x * 256 + tid;   // this thread: pix0 and pix0+128
    const int coBase = blockIdx.y * 16;

    float acc0[16], acc1[16];
#pragma unroll
    for (int i = 0; i < 16; i++) { acc0[i] = 0.f; acc1[i] = 0.f; }

    for (int k0 = 0; k0 < K; k0 += 8) {
        __syncthreads();
        {
            int kk = tid >> 4, co = tid & 15;
            s_w[kk][co] = wgt[(coBase + co) * K + k0 + kk];
        }
        __syncthreads();
#pragma unroll
        for (int kk = 0; kk < 8; kk++) {
            int k = k0 + kk;
            const float* p = (k < ksplit) ? (in0 + k * HWP)
                                          : (in1 + (k - ksplit) * HWP);
            float v0 = p[pix0], v1 = p[pix0 + 128];
#pragma unroll
            for (int co = 0; co < 16; co++) {
                acc0[co] = fmaf(v0, s_w[kk][co], acc0[co]);
                acc1[co] = fmaf(v1, s_w[kk][co], acc1[co]);
            }
        }
    }

#pragma unroll
    for (int co = 0; co < 16; co++) {
        float b = bias[coBase + co];
        float v0 = acc0[co] + b, v1 = acc1[co] + b;
        if (addsrc) {
            v0 += addsrc[(coBase + co) * HWP + pix0];
            v1 += addsrc[(coBase + co) * HWP + pix0 + 128];
        }
        out[(coBase + co) * HWP + pix0] = v0;
        out[(coBase + co) * HWP + pix0 + 128] = v1;
    }
}

// ---------------------------------------------------------------------------
// Host orchestration
// ---------------------------------------------------------------------------
extern "C" void kernel_launch(void* const* d_in, const int* in_sizes, int n_in,
                              void* d_out, int out_size)
{
    (void)in_sizes; (void)n_in; (void)out_size;

    const float* x = (const float*)d_in[0];
    // per-branch params: 0 dw,1 db,2 ow1,3 ob1,4 ow2,5 ob2,6 ow3,7 ob3,
    //                    8 ow4,9 ob4,10 bw1,11 bb1,12 bw2,13 bb2
    const float* P[2][14];
    for (int j = 0; j < 14; j++) {
        P[0][j] = (const float*)d_in[1 + j];    // backward
        P[1][j] = (const float*)d_in[15 + j];   // forward
    }
    const float* fus_w = (const float*)d_in[29];
    const float* fus_b = (const float*)d_in[30];
    float* out = (float*)d_out;

    float *fb, *ff, *hA, *hB, *o4, *cols, *dcn;
    cudaGetSymbolAddress((void**)&fb,  g_fb);
    cudaGetSymbolAddress((void**)&ff,  g_ff);
    cudaGetSymbolAddress((void**)&hA,  g_hA);
    cudaGetSymbolAddress((void**)&hB,  g_hB);
    cudaGetSymbolAddress((void**)&o4,  g_out4);
    cudaGetSymbolAddress((void**)&cols, g_cols);
    cudaGetSymbolAddress((void**)&dcn, g_dcn);

    const dim3 g64(36, 4);     // Cout=64
    const dim3 g432(36, 27);   // Cout=432

    for (int br = 0; br < 2; br++) {
        const float* const* p = P[br];
        float* F = (br == 0) ? fb : ff;     // branch feature storage
        const float* prop = nullptr;        // null == zeros

        for (int i = 0; i < 8; i++) {
            const int fr = (br == 0) ? (7 - i) : i;
            const float* cur = x + fr * CH;
            const float* n2 = nullptr;
            if (i > 1) {
                int fr2 = (br == 0) ? (7 - (i - 2)) : (i - 2);
                n2 = F + fr2 * CH;
            }

            if (i > 0) {
                // deform_align: offset/mask network on cond=[prop,cur,n2]
                conv3x3_k<<<g64, 128>>>(prop, cur, n2, 3, p[2], p[3], nullptr, hA, 1);
                conv3x3_k<<<g64, 128>>>(hA, nullptr, nullptr, 1, p[4], p[5], nullptr, hB, 1);
                conv3x3_k<<<g64, 128>>>(hB, nullptr, nullptr, 1, p[6], p[7], nullptr, hA, 1);
                conv3x3_k<<<g432, 128>>>(hA, nullptr, nullptr, 1, p[8], p[9], nullptr, o4, 0);
                // modulated deformable conv on xin=[prop, n2]
                dcn_sample_k<<<dim3(72, 144), 128>>>(prop, n2, o4, cols);
                gemm_k<<<g64, 128>>>(cols, cols, 1152, 1152, p[0], p[1], nullptr, dcn);
                prop = dcn;
            }

            // residual block: prop = prop + bw2(lrelu(bw1(feat)))
            if (br == 0)
                conv3x3_k<<<g64, 128>>>(cur, prop, nullptr, 2, p[10], p[11], nullptr, hA, 1);
            else
                conv3x3_k<<<g64, 128>>>(cur, fb + fr * CH, prop, 3, p[10], p[11], nullptr, hA, 1);
            conv3x3_k<<<g64, 128>>>(hA, nullptr, nullptr, 1, p[12], p[13], prop, F + fr * CH, 0);
            prop = F + fr * CH;
        }
    }

    // fusion: out[f] = conv1x1([fb[f], ff[f]]) + bias + x[f]
    for (int f = 0; f < 8; f++) {
        gemm_k<<<g64, 128>>>(fb + f * CH, ff + f * CH, 64, 128,
                             fus_w, fus_b, x + f * CH, out + f * CH);
    }
}

// round 3
// speedup vs baseline: 1.2237x; 1.2237x over previous
#include <cuda_runtime.h>
#include <math.h>

// ----------------------------------------------------------------------------
// BidirectionalPropagation (BasicVSR++ style) on GB300. B=1,T=8,C=64,96x96,DG=16
// R2: re-tiled conv3x3 (4px x 4cout per thread, FMA-bound, 288+ blocks),
//     re-tiled gemm (float2 loads, 8 couts, 288 blocks).
// ----------------------------------------------------------------------------

#define HWP 9216          // 96*96
#define CH  (64 * HWP)    // one 64-channel feature map

__device__ float g_fb[8][CH];
__device__ float g_ff[8][CH];
__device__ float g_hA[CH];
__device__ float g_hB[CH];
__device__ float g_out4[432 * HWP];
__device__ float g_cols[1152 * HWP];
__device__ float g_dcn[CH];

// ---------------------------------------------------------------------------
// conv3x3: tile 32x16 px, 128 threads. Thread = 4 x-consecutive px x 4 couts.
// 8-cin superblocks staged in smem. grid = (18, Cout/4).
// Per-cin per-warp: 54 LDS-cyc vs 72 FMA-cyc -> FMA-bound.
// ---------------------------------------------------------------------------
__global__ __launch_bounds__(128) void conv3x3_k(
    const float* __restrict__ in0, const float* __restrict__ in1,
    const float* __restrict__ in2, int cinBlocks,
    const float* __restrict__ wgt, const float* __restrict__ bias,
    const float* __restrict__ addsrc, float* __restrict__ out, int act)
{
    __shared__ float s_in[8 * 630];   // 8 cins x 18 rows x (34 cols, stride 35)
    __shared__ float s_w[8 * 36];     // 8 cins x 4 couts x 9 taps

    const int Cin = cinBlocks * 64;
    const int tid = threadIdx.x;
    const int tX = (blockIdx.x % 3) * 32;
    const int tY = (blockIdx.x / 3) * 16;
    const int coBase = blockIdx.y * 4;
    const int txg = tid & 7;          // x-group: pixels txg*4 .. txg*4+3
    const int ty  = tid >> 3;         // 0..15

    float acc[16];
#pragma unroll
    for (int i = 0; i < 16; i++) acc[i] = 0.f;

    const int nSuper = cinBlocks * 8;
    for (int s = 0; s < nSuper; s++) {
        const int cin0 = s * 8;
        const int blk = cin0 >> 6;
        const float* bp = (blk == 0) ? in0 : ((blk == 1) ? in1 : in2);
        __syncthreads();
        if (bp) {
            // stage 8 cins of 18x34 halo tile (padded stride 35)
            const float* bsrc = bp + (cin0 & 63) * HWP;
            for (int idx = tid; idx < 8 * 612; idx += 128) {
                int c = idx / 612; int rem = idx - c * 612;
                int r = rem / 34;  int cc = rem - r * 34;
                int gy = tY - 1 + r, gx = tX - 1 + cc;
                float v = 0.f;
                if ((unsigned)gy < 96u && (unsigned)gx < 96u)
                    v = bsrc[c * HWP + gy * 96 + gx];
                s_in[c * 630 + r * 35 + cc] = v;
            }
            // stage weights: 8 cins x 4 couts x 9
            for (int idx = tid; idx < 8 * 36; idx += 128) {
                int c = idx / 36; int rem = idx - c * 36;
                int co = rem / 9; int k = rem - co * 9;
                s_w[c * 36 + rem - co * 9 + co * 9] =
                    wgt[((coBase + co) * Cin + (cin0 + c)) * 9 + k];
            }
        }
        __syncthreads();
        if (!bp) continue;

#pragma unroll
        for (int c = 0; c < 8; c++) {
            const float* sp = s_in + c * 630 + ty * 35 + txg * 4;
            float iv[18];
#pragma unroll
            for (int r = 0; r < 3; r++)
#pragma unroll
                for (int cc = 0; cc < 6; cc++)
                    iv[r * 6 + cc] = sp[r * 35 + cc];
            const float* wp = s_w + c * 36;
#pragma unroll
            for (int co = 0; co < 4; co++) {
                float w[9];
#pragma unroll
                for (int k = 0; k < 9; k++) w[k] = wp[co * 9 + k];
#pragma unroll
                for (int r = 0; r < 3; r++)
#pragma unroll
                    for (int cc = 0; cc < 3; cc++) {
                        float wv = w[r * 3 + cc];
#pragma unroll
                        for (int j = 0; j < 4; j++)
                            acc[co * 4 + j] = fmaf(iv[r * 6 + cc + j], wv, acc[co * 4 + j]);
                    }
            }
        }
    }

    const int y = tY + ty;
    const int xb = tX + txg * 4;
    const int px = y * 96 + xb;
#pragma unroll
    for (int co = 0; co < 4; co++) {
        const float b = bias[coBase + co];
        float4 v;
        v.x = acc[co * 4 + 0] + b;
        v.y = acc[co * 4 + 1] + b;
        v.z = acc[co * 4 + 2] + b;
        v.w = acc[co * 4 + 3] + b;
        if (act) {
            v.x = (v.x >= 0.f) ? v.x : 0.1f * v.x;
            v.y = (v.y >= 0.f) ? v.y : 0.1f * v.y;
            v.z = (v.z >= 0.f) ? v.z : 0.1f * v.z;
            v.w = (v.w >= 0.f) ? v.w : 0.1f * v.w;
        }
        const int o = (coBase + co) * HWP + px;
        if (addsrc) {
            float4 a = *(const float4*)(addsrc + o);
            v.x += a.x; v.y += a.y; v.z += a.z; v.w += a.w;
        }
        *(float4*)(out + o) = v;
    }
}

// ---------------------------------------------------------------------------
// Modulated deformable sampling. grid = (72, 144) = (pix/128, dg*K).
// ---------------------------------------------------------------------------
__global__ __launch_bounds__(128) void dcn_sample_k(
    const float* __restrict__ xin0, const float* __restrict__ xin1,
    const float* __restrict__ out4, float* __restrict__ cols)
{
    const int pix = blockIdx.x * 128 + threadIdx.x;
    const int gk = blockIdx.y;           // g*9 + k
    const int g = gk / 9, k = gk - g * 9;
    const int h = pix / 96, w = pix - h * 96;

    const float offY = 5.f * tanhf(out4[(gk * 2 + 0) * HWP + pix]);
    const float offX = 5.f * tanhf(out4[(gk * 2 + 1) * HWP + pix]);
    const float mraw = out4[(288 + gk) * HWP + pix];
    const float m = 1.f / (1.f + expf(-mraw));

    const int ky = k / 3, kx = k - ky * 3;
    const float sy = offY + (float)(h - 1 + ky);
    const float sx = offX + (float)(w - 1 + kx);
    const float y0f = floorf(sy), x0f = floorf(sx);
    const float fy = sy - y0f, fx = sx - x0f;
    const int y0 = (int)y0f, x0 = (int)x0f;

    const bool vy0 = (y0 >= 0) && (y0 < 96);
    const bool vy1 = (y0 + 1 >= 0) && (y0 + 1 < 96);
    const bool vx0 = (x0 >= 0) && (x0 < 96);
    const bool vx1 = (x0 + 1 >= 0) && (x0 + 1 < 96);
    const int cy0 = min(max(y0, 0), 95), cy1 = min(max(y0 + 1, 0), 95);
    const int cx0 = min(max(x0, 0), 95), cx1 = min(max(x0 + 1, 0), 95);

    const float w00 = (1.f - fy) * (1.f - fx) * ((vy0 && vx0) ? 1.f : 0.f);
    const float w01 = (1.f - fy) * fx         * ((vy0 && vx1) ? 1.f : 0.f);
    const float w10 = fy * (1.f - fx)         * ((vy1 && vx0) ? 1.f : 0.f);
    const float w11 = fy * fx                 * ((vy1 && vx1) ? 1.f : 0.f);

    const int i00 = cy0 * 96 + cx0, i01 = cy0 * 96 + cx1;
    const int i10 = cy1 * 96 + cx0, i11 = cy1 * 96 + cx1;

#pragma unroll
    for (int c = 0; c < 8; c++) {
        const int cin = g * 8 + c;
        const float* p = (cin < 64) ? xin0 : xin1;
        float v = 0.f;
        if (p) {
            const float* pc = p + (cin & 63) * HWP;
            v = w00 * pc[i00] + w01 * pc[i01] + w10 * pc[i10] + w11 * pc[i11];
        }
        cols[(cin * 9 + k) * HWP + pix] = v * m;
    }
}

// ---------------------------------------------------------------------------
// GEMM: out[64,HWP] = W[64,K] @ in[K,HWP] + bias (+add).
// 128 threads, thread = 2 consecutive px (float2) x 8 couts. grid = (36, 8).
// ---------------------------------------------------------------------------
__global__ __launch_bounds__(128) void gemm_k(
    const float* __restrict__ in0, const float* __restrict__ in1,
    int ksplit, int K,
    const float* __restrict__ wgt, const float* __restrict__ bias,
    const float* __restrict__ addsrc, float* __restrict__ out)
{
    __shared__ float s_w[8][8];       // [kk][co]
    const int tid = threadIdx.x;
    const int pix0 = blockIdx.x * 256 + tid * 2;
    const int coBase = blockIdx.y * 8;

    float acc0[8], acc1[8];
#pragma unroll
    for (int i = 0; i < 8; i++) { acc0[i] = 0.f; acc1[i] = 0.f; }

    for (int k0 = 0; k0 < K; k0 += 8) {
        __syncthreads();
        if (tid < 64)
            s_w[tid >> 3][tid & 7] = wgt[(coBase + (tid & 7)) * K + k0 + (tid >> 3)];
        __syncthreads();
#pragma unroll
        for (int kk = 0; kk < 8; kk++) {
            const int k = k0 + kk;
            const float* p = (k < ksplit) ? (in0 + k * HWP)
                                          : (in1 + (k - ksplit) * HWP);
            const float2 v = *(const float2*)(p + pix0);
#pragma unroll
            for (int co = 0; co < 8; co++) {
                acc0[co] = fmaf(v.x, s_w[kk][co], acc0[co]);
                acc1[co] = fmaf(v.y, s_w[kk][co], acc1[co]);
            }
        }
    }

#pragma unroll
    for (int co = 0; co < 8; co++) {
        const float b = bias[coBase + co];
        float2 v; v.x = acc0[co] + b; v.y = acc1[co] + b;
        const int o = (coBase + co) * HWP + pix0;
        if (addsrc) {
            float2 a = *(const float2*)(addsrc + o);
            v.x += a.x; v.y += a.y;
        }
        *(float2*)(out + o) = v;
    }
}

// ---------------------------------------------------------------------------
// Host orchestration
// ---------------------------------------------------------------------------
extern "C" void kernel_launch(void* const* d_in, const int* in_sizes, int n_in,
                              void* d_out, int out_size)
{
    (void)in_sizes; (void)n_in; (void)out_size;

    const float* x = (const float*)d_in[0];
    const float* P[2][14];
    for (int j = 0; j < 14; j++) {
        P[0][j] = (const float*)d_in[1 + j];    // backward
        P[1][j] = (const float*)d_in[15 + j];   // forward
    }
    const float* fus_w = (const float*)d_in[29];
    const float* fus_b = (const float*)d_in[30];
    float* out = (float*)d_out;

    float *fb, *ff, *hA, *hB, *o4, *cols, *dcn;
    cudaGetSymbolAddress((void**)&fb,  g_fb);
    cudaGetSymbolAddress((void**)&ff,  g_ff);
    cudaGetSymbolAddress((void**)&hA,  g_hA);
    cudaGetSymbolAddress((void**)&hB,  g_hB);
    cudaGetSymbolAddress((void**)&o4,  g_out4);
    cudaGetSymbolAddress((void**)&cols, g_cols);
    cudaGetSymbolAddress((void**)&dcn, g_dcn);

    const dim3 gc64(18, 16);    // conv3x3, Cout=64
    const dim3 gc432(18, 108);  // conv3x3, Cout=432
    const dim3 gg64(36, 8);     // gemm, Cout=64

    for (int br = 0; br < 2; br++) {
        const float* const* p = P[br];
        float* F = (br == 0) ? fb : ff;
        const float* prop = nullptr;        // null == zeros

        for (int i = 0; i < 8; i++) {
            const int fr = (br == 0) ? (7 - i) : i;
            const float* cur = x + fr * CH;
            const float* n2 = nullptr;
            if (i > 1) {
                int fr2 = (br == 0) ? (7 - (i - 2)) : (i - 2);
                n2 = F + fr2 * CH;
            }

            if (i > 0) {
                conv3x3_k<<<gc64, 128>>>(prop, cur, n2, 3, p[2], p[3], nullptr, hA, 1);
                conv3x3_k<<<gc64, 128>>>(hA, nullptr, nullptr, 1, p[4], p[5], nullptr, hB, 1);
                conv3x3_k<<<gc64, 128>>>(hB, nullptr, nullptr, 1, p[6], p[7], nullptr, hA, 1);
                conv3x3_k<<<gc432, 128>>>(hA, nullptr, nullptr, 1, p[8], p[9], nullptr, o4, 0);
                dcn_sample_k<<<dim3(72, 144), 128>>>(prop, n2, o4, cols);
                gemm_k<<<gg64, 128>>>(cols, cols, 1152, 1152, p[0], p[1], nullptr, dcn);
                prop = dcn;
            }

            if (br == 0)
                conv3x3_k<<<gc64, 128>>>(cur, prop, nullptr, 2, p[10], p[11], nullptr, hA, 1);
            else
                conv3x3_k<<<gc64, 128>>>(cur, fb + fr * CH, prop, 3, p[10], p[11], nullptr, hA, 1);
            conv3x3_k<<<gc64, 128>>>(hA, nullptr, nullptr, 1, p[12], p[13], prop, F + fr * CH, 0);
            prop = F + fr * CH;
        }
    }

    for (int f = 0; f < 8; f++) {
        gemm_k<<<gg64, 128>>>(fb + f * CH, ff + f * CH, 64, 128,
                              fus_w, fus_b, x + f * CH, out + f * CH);
    }
}

// round 4
// speedup vs baseline: 1.8497x; 1.5116x over previous
#include <cuda_runtime.h>
#include <math.h>
#include <stdint.h>

// ----------------------------------------------------------------------------
// BidirectionalPropagation (BasicVSR++ style) on GB300. B=1,T=8,C=64,96x96,DG=16
// R3: conv3x3 with 3-stage cp.async pipeline (1 sync per 8-cin superblock),
//     precomputed staging addresses, float4 weight broadcasts.
// ----------------------------------------------------------------------------

#define HWP 9216          // 96*96
#define CH  (64 * HWP)

__device__ float g_fb[8][CH];
__device__ float g_ff[8][CH];
__device__ float g_hA[CH];
__device__ float g_hB[CH];
__device__ float g_out4[432 * HWP];
__device__ float g_cols[1152 * HWP];
__device__ float g_dcn[CH];

// conv smem stage: input 8 cins x 18 rows x 40 cols + weights 8 x 9 x 4
#define ROWW   40
#define CINSZ  (18 * ROWW)          // 720 floats per cin
#define SW_OFF (8 * CINSZ)          // 5760
#define STG_F  (SW_OFF + 288)       // 6048 floats per stage
#define NSTG   3
#define CONV_SMEM (NSTG * STG_F * 4)  // 72576 bytes

__device__ __forceinline__ void cp16(uint32_t d, const void* g, int sz) {
    asm volatile("cp.async.ca.shared.global [%0], [%1], 16, %2;\n"
                 :: "r"(d), "l"(g), "r"(sz));
}
__device__ __forceinline__ void cp4(uint32_t d, const void* g) {
    asm volatile("cp.async.ca.shared.global [%0], [%1], 4;\n"
                 :: "r"(d), "l"(g));
}
#define CP_COMMIT() asm volatile("cp.async.commit_group;\n" ::: "memory")
#define CP_WAIT1()  asm volatile("cp.async.wait_group 1;\n" ::: "memory")

// ---------------------------------------------------------------------------
// conv3x3: tile 32x16 px, 128 threads, thread = 4 consecutive px x 4 couts.
// grid = (18, Cout/4). Up to three 64-ch input blocks (nullptr => zeros).
// ---------------------------------------------------------------------------
__global__ __launch_bounds__(128) void conv3x3_k(
    const float* __restrict__ in0, const float* __restrict__ in1,
    const float* __restrict__ in2, int cinBlocks,
    const float* __restrict__ wgt, const float* __restrict__ bias,
    const float* __restrict__ addsrc, float* __restrict__ out, int act)
{
    extern __shared__ float smem[];
    const int tid = threadIdx.x;
    const int tX = (blockIdx.x % 3) * 32;
    const int tY = (blockIdx.x / 3) * 16;
    const int coBase = blockIdx.y * 4;
    const int txg = tid & 7;
    const int ty  = tid >> 3;
    const int Cin = cinBlocks * 64;

    // compact list of non-null input blocks
    const float* ptrs[3] = {in0, in1, in2};
    const float* actp[3]; int actc[3]; int na = 0;
    for (int b = 0; b < cinBlocks; b++)
        if (ptrs[b]) { actp[na] = ptrs[b]; actc[na] = b * 64; na++; }
    const int nSuper = na * 8;

    // ---- precompute staging tuples (fixed across superblocks) ----
    // input: 1440 float4 slots; slot = c*180 + r*10 + q
    int in_goff[12]; unsigned in_val = 0;
#pragma unroll
    for (int i = 0; i < 12; i++) {
        int slot = tid + i * 128;
        int c = slot / 180; int rem = slot - c * 180;
        int r = rem / 10;   int q = rem - r * 10;
        int gy = tY - 1 + r, gx = tX - 4 + q * 4;
        bool v = ((unsigned)gy < 96u) && ((unsigned)gx < 96u);
        in_goff[i] = v ? (c * HWP + gy * 96 + gx) : 0;
        if (v) in_val |= (1u << i);
    }
    // weights: 288 scalar slots; slot = c*36 + k*4 + co
    int w_goff[3];
#pragma unroll
    for (int i = 0; i < 3; i++) {
        int slot = tid + i * 128;
        if (slot < 288) {
            int c = slot / 36; int rem = slot - c * 36;
            int k = rem >> 2;  int co = rem & 3;
            w_goff[i] = ((coBase + co) * Cin + c) * 9 + k;
        } else w_goff[i] = 0;
    }

    const uint32_t s32 = (uint32_t)__cvta_generic_to_shared(smem);

    auto PREFETCH = [&](int sb, int stg) {
        const float* base = actp[sb >> 3] + ((sb & 7) * 8) * HWP;
        const uint32_t d0 = s32 + (uint32_t)stg * (STG_F * 4) + tid * 16;
#pragma unroll
        for (int i = 0; i < 11; i++)
            cp16(d0 + i * 2048, base + in_goff[i], ((in_val >> i) & 1) ? 16 : 0);
        if (tid < 32)
            cp16(d0 + 11 * 2048, base + in_goff[11], ((in_val >> 11) & 1) ? 16 : 0);
        const float* wbase = wgt + (actc[sb >> 3] + (sb & 7) * 8) * 9;
        const uint32_t w0 = s32 + (uint32_t)stg * (STG_F * 4) + SW_OFF * 4 + tid * 4;
        cp4(w0,            wbase + w_goff[0]);
        cp4(w0 + 128 * 4,  wbase + w_goff[1]);
        if (tid < 32) cp4(w0 + 256 * 4, wbase + w_goff[2]);
    };

    float acc[16];
#pragma unroll
    for (int i = 0; i < 16; i++) acc[i] = 0.f;

    // prologue: stages 0 and 1 (nSuper >= 8 always)
    PREFETCH(0, 0); CP_COMMIT();
    PREFETCH(1, 1); CP_COMMIT();

    int stg = 0, pstg = 2;
    for (int s = 0; s < nSuper; s++) {
        CP_WAIT1();
        __syncthreads();
        const float* st = smem + stg * STG_F;

#pragma unroll
        for (int c = 0; c < 8; c++) {
            const float* sp = st + c * CINSZ + ty * ROWW + txg * 4;
            float iv[18];
#pragma unroll
            for (int r = 0; r < 3; r++) {
                const float4 m = *(const float4*)(sp + r * ROWW + 4);
                iv[r * 6 + 0] = sp[r * ROWW + 3];
                iv[r * 6 + 1] = m.x; iv[r * 6 + 2] = m.y;
                iv[r * 6 + 3] = m.z; iv[r * 6 + 4] = m.w;
                iv[r * 6 + 5] = sp[r * ROWW + 8];
            }
            const float* wp = st + SW_OFF + c * 36;
#pragma unroll
            for (int k9 = 0; k9 < 9; k9++) {
                const float4 wv = *(const float4*)(wp + k9 * 4);
                const int r = k9 / 3, cc = k9 - r * 3;
#pragma unroll
                for (int j = 0; j < 4; j++) {
                    const float x = iv[r * 6 + cc + j];
                    acc[0  + j] = fmaf(x, wv.x, acc[0  + j]);
                    acc[4  + j] = fmaf(x, wv.y, acc[4  + j]);
                    acc[8  + j] = fmaf(x, wv.z, acc[8  + j]);
                    acc[12 + j] = fmaf(x, wv.w, acc[12 + j]);
                }
            }
        }

        if (s + 2 < nSuper) PREFETCH(s + 2, pstg);
        CP_COMMIT();
        stg = (stg == 2) ? 0 : stg + 1;
        pstg = (pstg == 2) ? 0 : pstg + 1;
    }

    const int y = tY + ty;
    const int xb = tX + txg * 4;
    const int px = y * 96 + xb;
#pragma unroll
    for (int co = 0; co < 4; co++) {
        const float b = bias[coBase + co];
        float4 v;
        v.x = acc[co * 4 + 0] + b;
        v.y = acc[co * 4 + 1] + b;
        v.z = acc[co * 4 + 2] + b;
        v.w = acc[co * 4 + 3] + b;
        if (act) {
            v.x = (v.x >= 0.f) ? v.x : 0.1f * v.x;
            v.y = (v.y >= 0.f) ? v.y : 0.1f * v.y;
            v.z = (v.z >= 0.f) ? v.z : 0.1f * v.z;
            v.w = (v.w >= 0.f) ? v.w : 0.1f * v.w;
        }
        const int o = (coBase + co) * HWP + px;
        if (addsrc) {
            float4 a = *(const float4*)(addsrc + o);
            v.x += a.x; v.y += a.y; v.z += a.z; v.w += a.w;
        }
        *(float4*)(out + o) = v;
    }
}

// ---------------------------------------------------------------------------
// Modulated deformable sampling. grid = (72, 144) = (pix/128, dg*K).
// ---------------------------------------------------------------------------
__global__ __launch_bounds__(128) void dcn_sample_k(
    const float* __restrict__ xin0, const float* __restrict__ xin1,
    const float* __restrict__ out4, float* __restrict__ cols)
{
    const int pix = blockIdx.x * 128 + threadIdx.x;
    const int gk = blockIdx.y;
    const int g = gk / 9, k = gk - g * 9;
    const int h = pix / 96, w = pix - h * 96;

    const float offY = 5.f * tanhf(out4[(gk * 2 + 0) * HWP + pix]);
    const float offX = 5.f * tanhf(out4[(gk * 2 + 1) * HWP + pix]);
    const float mraw = out4[(288 + gk) * HWP + pix];
    const float m = 1.f / (1.f + expf(-mraw));

    const int ky = k / 3, kx = k - ky * 3;
    const float sy = offY + (float)(h - 1 + ky);
    const float sx = offX + (float)(w - 1 + kx);
    const float y0f = floorf(sy), x0f = floorf(sx);
    const float fy = sy - y0f, fx = sx - x0f;
    const int y0 = (int)y0f, x0 = (int)x0f;

    const bool vy0 = (y0 >= 0) && (y0 < 96);
    const bool vy1 = (y0 + 1 >= 0) && (y0 + 1 < 96);
    const bool vx0 = (x0 >= 0) && (x0 < 96);
    const bool vx1 = (x0 + 1 >= 0) && (x0 + 1 < 96);
    const int cy0 = min(max(y0, 0), 95), cy1 = min(max(y0 + 1, 0), 95);
    const int cx0 = min(max(x0, 0), 95), cx1 = min(max(x0 + 1, 0), 95);

    const float w00 = (1.f - fy) * (1.f - fx) * ((vy0 && vx0) ? 1.f : 0.f);
    const float w01 = (1.f - fy) * fx         * ((vy0 && vx1) ? 1.f : 0.f);
    const float w10 = fy * (1.f - fx)         * ((vy1 && vx0) ? 1.f : 0.f);
    const float w11 = fy * fx                 * ((vy1 && vx1) ? 1.f : 0.f);

    const int i00 = cy0 * 96 + cx0, i01 = cy0 * 96 + cx1;
    const int i10 = cy1 * 96 + cx0, i11 = cy1 * 96 + cx1;

#pragma unroll
    for (int c = 0; c < 8; c++) {
        const int cin = g * 8 + c;
        const float* p = (cin < 64) ? xin0 : xin1;
        float v = 0.f;
        if (p) {
            const float* pc = p + (cin & 63) * HWP;
            v = w00 * pc[i00] + w01 * pc[i01] + w10 * pc[i10] + w11 * pc[i11];
        }
        cols[(cin * 9 + k) * HWP + pix] = v * m;
    }
}

// ---------------------------------------------------------------------------
// GEMM: out[64,HWP] = W[64,K] @ in[K,HWP] + bias (+add). grid = (36, 8).
// ---------------------------------------------------------------------------
__global__ __launch_bounds__(128) void gemm_k(
    const float* __restrict__ in0, const float* __restrict__ in1,
    int ksplit, int K,
    const float* __restrict__ wgt, const float* __restrict__ bias,
    const float* __restrict__ addsrc, float* __restrict__ out)
{
    __shared__ float s_w[8][8];
    const int tid = threadIdx.x;
    const int pix0 = blockIdx.x * 256 + tid * 2;
    const int coBase = blockIdx.y * 8;

    float acc0[8], acc1[8];
#pragma unroll
    for (int i = 0; i < 8; i++) { acc0[i] = 0.f; acc1[i] = 0.f; }

    for (int k0 = 0; k0 < K; k0 += 8) {
        __syncthreads();
        if (tid < 64)
            s_w[tid >> 3][tid & 7] = wgt[(coBase + (tid & 7)) * K + k0 + (tid >> 3)];
        __syncthreads();
#pragma unroll
        for (int kk = 0; kk < 8; kk++) {
            const int k = k0 + kk;
            const float* p = (k < ksplit) ? (in0 + k * HWP)
                                          : (in1 + (k - ksplit) * HWP);
            const float2 v = *(const float2*)(p + pix0);
#pragma unroll
            for (int co = 0; co < 8; co++) {
                acc0[co] = fmaf(v.x, s_w[kk][co], acc0[co]);
                acc1[co] = fmaf(v.y, s_w[kk][co], acc1[co]);
            }
        }
    }

#pragma unroll
    for (int co = 0; co < 8; co++) {
        const float b = bias[coBase + co];
        float2 v; v.x = acc0[co] + b; v.y = acc1[co] + b;
        const int o = (coBase + co) * HWP + pix0;
        if (addsrc) {
            float2 a = *(const float2*)(addsrc + o);
            v.x += a.x; v.y += a.y;
        }
        *(float2*)(out + o) = v;
    }
}

// ---------------------------------------------------------------------------
// Host orchestration
// ---------------------------------------------------------------------------
extern "C" void kernel_launch(void* const* d_in, const int* in_sizes, int n_in,
                              void* d_out, int out_size)
{
    (void)in_sizes; (void)n_in; (void)out_size;

    cudaFuncSetAttribute(conv3x3_k, cudaFuncAttributeMaxDynamicSharedMemorySize,
                         CONV_SMEM);

    const float* x = (const float*)d_in[0];
    const float* P[2][14];
    for (int j = 0; j < 14; j++) {
        P[0][j] = (const float*)d_in[1 + j];
        P[1][j] = (const float*)d_in[15 + j];
    }
    const float* fus_w = (const float*)d_in[29];
    const float* fus_b = (const float*)d_in[30];
    float* out = (float*)d_out;

    float *fb, *ff, *hA, *hB, *o4, *cols, *dcn;
    cudaGetSymbolAddress((void**)&fb,  g_fb);
    cudaGetSymbolAddress((void**)&ff,  g_ff);
    cudaGetSymbolAddress((void**)&hA,  g_hA);
    cudaGetSymbolAddress((void**)&hB,  g_hB);
    cudaGetSymbolAddress((void**)&o4,  g_out4);
    cudaGetSymbolAddress((void**)&cols, g_cols);
    cudaGetSymbolAddress((void**)&dcn, g_dcn);

    const dim3 gc64(18, 16);
    const dim3 gc432(18, 108);
    const dim3 gg64(36, 8);

    for (int br = 0; br < 2; br++) {
        const float* const* p = P[br];
        float* F = (br == 0) ? fb : ff;
        const float* prop = nullptr;

        for (int i = 0; i < 8; i++) {
            const int fr = (br == 0) ? (7 - i) : i;
            const float* cur = x + fr * CH;
            const float* n2 = nullptr;
            if (i > 1) {
                int fr2 = (br == 0) ? (7 - (i - 2)) : (i - 2);
                n2 = F + fr2 * CH;
            }

            if (i > 0) {
                conv3x3_k<<<gc64, 128, CONV_SMEM>>>(prop, cur, n2, 3, p[2], p[3], nullptr, hA, 1);
                conv3x3_k<<<gc64, 128, CONV_SMEM>>>(hA, nullptr, nullptr, 1, p[4], p[5], nullptr, hB, 1);
                conv3x3_k<<<gc64, 128, CONV_SMEM>>>(hB, nullptr, nullptr, 1, p[6], p[7], nullptr, hA, 1);
                conv3x3_k<<<gc432, 128, CONV_SMEM>>>(hA, nullptr, nullptr, 1, p[8], p[9], nullptr, o4, 0);
                dcn_sample_k<<<dim3(72, 144), 128>>>(prop, n2, o4, cols);
                gemm_k<<<gg64, 128>>>(cols, cols, 1152, 1152, p[0], p[1], nullptr, dcn);
                prop = dcn;
            }

            if (br == 0)
                conv3x3_k<<<gc64, 128, CONV_SMEM>>>(cur, prop, nullptr, 2, p[10], p[11], nullptr, hA, 1);
            else
                conv3x3_k<<<gc64, 128, CONV_SMEM>>>(cur, fb + fr * CH, prop, 3, p[10], p[11], nullptr, hA, 1);
            conv3x3_k<<<gc64, 128, CONV_SMEM>>>(hA, nullptr, nullptr, 1, p[12], p[13], prop, F + fr * CH, 0);
            prop = F + fr * CH;
        }
    }

    for (int f = 0; f < 8; f++) {
        gemm_k<<<gg64, 128>>>(fb + f * CH, ff + f * CH, 64, 128,
                              fus_w, fus_b, x + f * CH, out + f * CH);
    }
}